// round 13
// baseline (speedup 1.0000x reference)
#include <cuda_runtime.h>

#define TT 32
#define PP 16
#define NN 65536
#define HH 128
#define NTHREADS 128
#define NBLOCKS 256   // 256*128 threads; lane-pairs share 4 points -> 65536 pts

#define OFF_ARG (TT * NN * 3)      // 6291456
#define OFF_TL  (OFF_ARG + NN)     // 6356992

__device__ __forceinline__ unsigned long long packrep(float a) {
    unsigned long long r;
    asm("mov.b64 %0, {%1, %1};" : "=l"(r) : "f"(a));
    return r;
}
__device__ __forceinline__ void fma2(unsigned long long& d, unsigned long long a, unsigned long long b) {
    asm("fma.rn.f32x2 %0, %1, %2, %0;" : "+l"(d) : "l"(a), "l"(b));
}
__device__ __forceinline__ void unpack2(unsigned long long v, float& lo, float& hi) {
    asm("mov.b64 {%0, %1}, %2;" : "=f"(lo), "=f"(hi) : "l"(v));
}

__global__ void __launch_bounds__(NTHREADS) fused_kernel(
    const float* __restrict__ cano, const float* __restrict__ w1,
    const float* __restrict__ b1, const float* __restrict__ w2,
    const float* __restrict__ b2, const float* __restrict__ p6d,
    const float* __restrict__ pt, const float* __restrict__ gum,
    float* __restrict__ out)
{
    __shared__ float4 s_w1[HH];                        // w1 row + b1
    __shared__ __align__(16) float4 s_w2[HH][2][2];    // [h][half][j]: experts 8*half+4j..+3
    __shared__ __align__(16) float s_R[TT * PP][12];   // R rows + t

    const int tid = threadIdx.x;

    // ---- stage weights ----
    s_w1[tid] = make_float4(w1[3 * tid], w1[3 * tid + 1], w1[3 * tid + 2], b1[tid]);
    #pragma unroll
    for (int k = 0; k < 4; k++) {           // 512 float4 slots / 128 threads
        int idx = k * NTHREADS + tid;       // 0..511 = h*4 + (half*2+j)
        int h = idx >> 2;
        int hf = (idx >> 1) & 1;
        int j = idx & 1;
        int e0 = 8 * hf + 4 * j;
        s_w2[h][hf][j] = make_float4(w2[(e0 + 0) * HH + h], w2[(e0 + 1) * HH + h],
                                     w2[(e0 + 2) * HH + h], w2[(e0 + 3) * HH + h]);
    }

    // ---- per-block rotation table ----
    #pragma unroll
    for (int k = 0; k < 4; k++) {
        int e = k * NTHREADS + tid;         // 0..511 = t*16+p
        float a1x = p6d[e * 6 + 0], a1y = p6d[e * 6 + 1], a1z = p6d[e * 6 + 2];
        float a2x = p6d[e * 6 + 3], a2y = p6d[e * 6 + 4], a2z = p6d[e * 6 + 5];
        float inv = rsqrtf(a1x * a1x + a1y * a1y + a1z * a1z);
        float b1x = a1x * inv, b1y = a1y * inv, b1z = a1z * inv;
        float d = b1x * a2x + b1y * a2y + b1z * a2z;
        float cx = a2x - d * b1x, cy = a2y - d * b1y, cz = a2z - d * b1z;
        float inv2 = rsqrtf(cx * cx + cy * cy + cz * cz);
        float b2x = cx * inv2, b2y = cy * inv2, b2z = cz * inv2;
        float b3x = b1y * b2z - b1z * b2y;
        float b3y = b1z * b2x - b1x * b2z;
        float b3z = b1x * b2y - b1y * b2x;
        float t0 = pt[e * 3 + 0], t1 = pt[e * 3 + 1], t2 = pt[e * 3 + 2];
        float* r = s_R[e];
        r[0] = b1x; r[1] = b1y; r[2] = b1z;
        r[3] = b2x; r[4] = b2y; r[5] = b2z;
        r[6] = b3x; r[7] = b3y; r[8] = b3z;
        r[9] = t0;  r[10] = t1; r[11] = t2;
        if (blockIdx.x == 0) {
            float* o = out + OFF_TL + e * 16;
            o[0] = b1x; o[1] = b1y; o[2]  = b1z; o[3]  = t0;
            o[4] = b2x; o[5] = b2y; o[6]  = b2z; o[7]  = t1;
            o[8] = b3x; o[9] = b3y; o[10] = b3z; o[11] = t2;
            o[12] = 0.f; o[13] = 0.f; o[14] = 0.f; o[15] = 1.f;
        }
    }

    // ---- lane-pair layout: pair (2k,2k+1) shares 4 points, splits experts ----
    const int gtid = blockIdx.x * NTHREADS + tid;
    const int q = gtid >> 1;        // pair id: 0..16383
    const int half = gtid & 1;      // 0: experts 0-7, 1: experts 8-15
    const int n0 = q * 4;           // first of 4 shared points

    // points: 48 floats?? no — 12 floats = 3 float4; byte offset 48q -> 16-aligned
    const float4* c4 = reinterpret_cast<const float4*>(cano + (size_t)n0 * 3);
    float4 ca = c4[0], cb = c4[1], cc = c4[2];
    float px[4], py[4], pz[4];
    px[0] = ca.x; py[0] = ca.y; pz[0] = ca.z;
    px[1] = ca.w; py[1] = cb.x; pz[1] = cb.y;
    px[2] = cb.z; py[2] = cb.w; pz[2] = cc.x;
    px[3] = cc.y; py[3] = cc.z; pz[3] = cc.w;

    // bias for my 8 experts (4 f32x2 pairs)
    unsigned long long seg[4][4];
    {
        const unsigned long long* b2p =
            reinterpret_cast<const unsigned long long*>(b2 + 8 * half);
        unsigned long long bb0 = b2p[0], bb1 = b2p[1], bb2 = b2p[2], bb3 = b2p[3];
        #pragma unroll
        for (int k = 0; k < 4; k++) {
            seg[k][0] = bb0; seg[k][1] = bb1; seg[k][2] = bb2; seg[k][3] = bb3;
        }
    }

    __syncthreads();

    // ---- MLP: 3 LDS.128/iter for 4 points ----
    #pragma unroll 4
    for (int h = 0; h < HH; h++) {
        float4 w = s_w1[h];
        ulonglong2 u0 = *reinterpret_cast<const ulonglong2*>(&s_w2[h][half][0]);
        #pragma unroll
        for (int k = 0; k < 4; k++) {
            float hv = fmaxf(fmaf(px[k], w.x, fmaf(py[k], w.y, fmaf(pz[k], w.z, w.w))), 0.0f);
            unsigned long long h2 = packrep(hv);
            fma2(seg[k][0], h2, u0.x);
            fma2(seg[k][1], h2, u0.y);
        }
        ulonglong2 u1 = *reinterpret_cast<const ulonglong2*>(&s_w2[h][half][1]);
        #pragma unroll
        for (int k = 0; k < 4; k++) {
            float hv = fmaxf(fmaf(px[k], w.x, fmaf(py[k], w.y, fmaf(pz[k], w.z, w.w))), 0.0f);
            unsigned long long h2 = packrep(hv);
            fma2(seg[k][2], h2, u1.x);
            fma2(seg[k][3], h2, u1.y);
        }
    }

    // ---- per-point: local argmax over my 8 experts, then pair-combine via shfl ----
    int sel[4];
    float argm[4];
    #pragma unroll
    for (int k = 0; k < 4; k++) {
        float s[8];
        unpack2(seg[k][0], s[0], s[1]);
        unpack2(seg[k][1], s[2], s[3]);
        unpack2(seg[k][2], s[4], s[5]);
        unpack2(seg[k][3], s[6], s[7]);

        // seg argmax (output 2), local over 8; global idx = 8*half + j
        int ia = 0; float ma = s[0];
        #pragma unroll
        for (int j = 1; j < 8; j++)
            if (s[j] > ma) { ma = s[j]; ia = j; }
        float iaf = (float)(8 * half + ia);

        // gumbel for my half: gum[n*16 + 8*half], 16-aligned
        const float4* g4 =
            reinterpret_cast<const float4*>(gum + (size_t)(n0 + k) * PP + 8 * half);
        float4 g0 = g4[0], g1 = g4[1];
        const float gg[8] = { g0.x, g0.y, g0.z, g0.w, g1.x, g1.y, g1.z, g1.w };
        int is = 0; float ms = s[0] + gg[0];
        #pragma unroll
        for (int j = 1; j < 8; j++) {
            float a = s[j] + gg[j];
            if (a > ms) { ms = a; is = j; }
        }
        float isf = (float)(8 * half + is);

        // pair exchange (lanes 2k <-> 2k+1); tie -> lower index (first occurrence)
        float o_ma  = __shfl_xor_sync(0xffffffffu, ma,  1);
        float o_iaf = __shfl_xor_sync(0xffffffffu, iaf, 1);
        float o_ms  = __shfl_xor_sync(0xffffffffu, ms,  1);
        float o_isf = __shfl_xor_sync(0xffffffffu, isf, 1);
        if (o_ma > ma || (o_ma == ma && o_iaf < iaf)) { ma = o_ma; iaf = o_iaf; }
        if (o_ms > ms || (o_ms == ms && o_isf < isf)) { ms = o_ms; isf = o_isf; }
        argm[k] = iaf;
        sel[k] = (int)isf;
    }

    // argmax store: one thread per pair, float4 at 16q bytes (aligned)
    if (half == 0)
        *reinterpret_cast<float4*>(out + OFF_ARG + n0) =
            make_float4(argm[0], argm[1], argm[2], argm[3]);

    // ---- epilogue: pair splits t-range 16/16; 3 float4 stores per t (aligned) ----
    #pragma unroll 2
    for (int tt = 0; tt < 16; tt++) {
        const int t = half * 16 + tt;
        float o[4][3];
        #pragma unroll
        for (int k = 0; k < 4; k++) {
            const float4* R = reinterpret_cast<const float4*>(s_R[t * PP + sel[k]]);
            float4 r0 = R[0], r1 = R[1], r2 = R[2];
            o[k][0] = fmaf(px[k], r0.x, fmaf(py[k], r0.y, fmaf(pz[k], r0.z, r2.y)));
            o[k][1] = fmaf(px[k], r0.w, fmaf(py[k], r1.x, fmaf(pz[k], r1.y, r2.z)));
            o[k][2] = fmaf(px[k], r1.z, fmaf(py[k], r1.w, fmaf(pz[k], r2.x, r2.w)));
        }
        float4* dst = reinterpret_cast<float4*>(out + (size_t)(t * NN + n0) * 3);
        dst[0] = make_float4(o[0][0], o[0][1], o[0][2], o[1][0]);
        dst[1] = make_float4(o[1][1], o[1][2], o[2][0], o[2][1]);
        dst[2] = make_float4(o[2][2], o[3][0], o[3][1], o[3][2]);
    }
}

extern "C" void kernel_launch(void* const* d_in, const int* in_sizes, int n_in,
                              void* d_out, int out_size) {
    (void)in_sizes; (void)n_in; (void)out_size;
    fused_kernel<<<NBLOCKS, NTHREADS>>>(
        (const float*)d_in[0],  // cano_pc
        (const float*)d_in[1],  // w1
        (const float*)d_in[2],  // b1
        (const float*)d_in[3],  // w2
        (const float*)d_in[4],  // b2
        (const float*)d_in[5],  // proposal_6d
        (const float*)d_in[6],  // proposal_t
        (const float*)d_in[7],  // gumbel
        (float*)d_out);
}